// round 11
// baseline (speedup 1.0000x reference)
#include <cuda_runtime.h>

#define NODES  8448
#define NB     10
#define ITERS  5
#define TPB    1024
#define NPTMAX 9             // ceil(8448/1024); threads 0..255 do 9, rest do 8
#define NBATCH 1024
#define RPC    4             // batch rows per CTA (packed as float4)
#define NGROUPS (NBATCH / RPC)   // 256
#define NQG    (NODES / 8)   // 1056 quarter-warp node groups

#define SMEM_BYTES (NODES * 16)  // float4 tanh table = 135168 B

// Global scratch (static __device__ arrays; no allocation).
__device__ unsigned int g_pk[5][NODES];       // u16 neighbor ids, 2-per-u32, slot-SoA
__device__ float4       g_wllr[NGROUPS][NODES];
__device__ float4       g_P[NGROUPS][NODES];  // vm_{t-1}

// ---------------------------------------------------------------------------
// Prep: one warp per 8-node group; threads 0..9 own slot counters; argmin over
// slots via a single __reduce_min_sync. Bit-identical schedule to R7 greedy.
__global__ void prep_sched_kernel(const int* __restrict__ check_idx)
{
    const int warp = (blockIdx.x * blockDim.x + threadIdx.x) >> 5;
    const int lane = threadIdx.x & 31;
    if (warp >= NQG) return;

    const int base = warp * 80;          // 8 nodes * 10 indices
    const unsigned v0 = (unsigned)check_idx[base + lane];
    const unsigned v1 = (unsigned)check_idx[base + 32 + lane];
    const unsigned v2 = (lane < 16) ? (unsigned)check_idx[base + 64 + lane] : 0u;

    const bool is_slot = (lane < 10);
    unsigned cnt = 0u;                   // my slot's 8 nibble bank-group counts

    #pragma unroll
    for (int ln = 0; ln < 8; ln++) {
        unsigned taken = 0u;
        unsigned perm  = 0u;

        #pragma unroll
        for (int j = 0; j < 10; j++) {
            const int flat = ln * 10 + j;          // compile-time constant
            unsigned v;
            if      (flat < 32) v = __shfl_sync(0xFFFFFFFFu, v0, flat);
            else if (flat < 64) v = __shfl_sync(0xFFFFFFFFu, v1, flat - 32);
            else                v = __shfl_sync(0xFFFFFFFFu, v2, flat - 64);

            const unsigned sh = (v & 7u) * 4u;
            const unsigned c  = (cnt >> sh) & 0xFu;
            const unsigned key = (is_slot && !taken) ? ((c << 8) | (unsigned)lane)
                                                     : 0xFFFFu;
            const unsigned best = __reduce_min_sync(0xFFFFFFFFu, key) & 0xFFu;
            if ((unsigned)lane == best) {
                taken = 1u;
                cnt  += 1u << sh;
                perm  = v;
            }
        }
        const unsigned plo = __shfl_sync(0xFFFFFFFFu, perm, (lane << 1), 32);
        const unsigned phi = __shfl_sync(0xFFFFFFFFu, perm, (lane << 1) + 1, 32);
        if (lane < 5)
            g_pk[lane][warp * 8 + ln] = (plo & 0xFFFFu) | (phi << 16);
    }
}

// ---------------------------------------------------------------------------
// Fast transcendentals (MUFU-based, rel err ~3e-6 each):
// tanh(clip(0.5*v, -9.9, 9.9)) = 1 - 2/(1 + e^{clip(v, -19.8, 19.8)})
__device__ __forceinline__ float fast_tanh_half(float v)
{
    const float x = fminf(19.8f, fmaxf(-19.8f, v));
    const float e = __expf(x);
    return fmaf(-2.0f, __frcp_rn(1.0f + e), 1.0f);
}
__device__ __forceinline__ float fast_2atanh(float p)
{
    p = fminf(0.999999f, fmaxf(-0.999999f, p));
    return __logf(__fdividef(1.0f + p, 1.0f - p));
}
__device__ __forceinline__ float fast_sigmoid(float z)
{
    return __frcp_rn(1.0f + __expf(-z));
}

// ---------------------------------------------------------------------------
__global__ __launch_bounds__(TPB, 1)
void ldpc4_kernel(const float* __restrict__ input_llr,
                  const float* __restrict__ w_ch,
                  const float* __restrict__ w_res,   // (2, NODES)
                  float*       __restrict__ out)
{
    extern __shared__ float4 st[];                   // tanh values, 4 rows packed
    const int tid  = threadIdx.x;
    const int g    = blockIdx.x;
    const int row0 = g * RPC;
    const float* llr0 = input_llr + (size_t)row0 * NODES;

    float4 cur[NPTMAX];   // current var_messages for this thread's nodes (4 rows)

    // Prologue: weighted LLR -> registers + global scratch.
    #pragma unroll
    for (int i = 0; i < NPTMAX; i++) {
        const int n = tid + i * TPB;
        if (n < NODES) {
            const float wc = w_ch[n];
            float4 wl;
            wl.x = llr0[n]             * wc;
            wl.y = llr0[NODES + n]     * wc;
            wl.z = llr0[2 * NODES + n] * wc;
            wl.w = llr0[3 * NODES + n] * wc;
            g_wllr[g][n] = wl;
            cur[i] = wl;
        }
    }

    for (int it = 0; it < ITERS; it++) {
        // Phase A: publish t = tanh(clip(0.5 * vm)) for all 4 rows (one STS.128).
        #pragma unroll
        for (int i = 0; i < NPTMAX; i++) {
            const int n = tid + i * TPB;
            if (n < NODES) {
                const float4 v = cur[i];
                float4 t;
                t.x = fast_tanh_half(v.x);
                t.y = fast_tanh_half(v.y);
                t.z = fast_tanh_half(v.z);
                t.w = fast_tanh_half(v.w);
                st[n] = t;
            }
        }
        __syncthreads();

        // Phase B: gather 10 scheduled neighbors (LDS.128 serves 4 rows),
        // product, 2*atanh, residual, update.
        #pragma unroll 2
        for (int i = 0; i < NPTMAX; i++) {
            const int n = tid + i * TPB;
            if (n < NODES) {
                const unsigned pk0 = g_pk[0][n], pk1 = g_pk[1][n];
                const unsigned pk2 = g_pk[2][n], pk3 = g_pk[3][n];
                const unsigned pk4 = g_pk[4][n];

                // prefetch iteration-state (L2 latency overlaps LDS work)
                float4 pr = make_float4(0.f, 0.f, 0.f, 0.f);
                if (it > 0) pr = g_P[g][n];
                const float4 wl = g_wllr[g][n];
                const float  w0 = w_res[n];
                const float  w1 = w_res[NODES + n];

                float4 p0 = st[pk0 & 0xFFFFu];
                float4 p1 = st[pk0 >> 16];
                {
                    const float4 a = st[pk1 & 0xFFFFu];
                    const float4 b = st[pk1 >> 16];
                    p0.x *= a.x; p0.y *= a.y; p0.z *= a.z; p0.w *= a.w;
                    p1.x *= b.x; p1.y *= b.y; p1.z *= b.z; p1.w *= b.w;
                }
                {
                    const float4 a = st[pk2 & 0xFFFFu];
                    const float4 b = st[pk2 >> 16];
                    p0.x *= a.x; p0.y *= a.y; p0.z *= a.z; p0.w *= a.w;
                    p1.x *= b.x; p1.y *= b.y; p1.z *= b.z; p1.w *= b.w;
                }
                {
                    const float4 a = st[pk3 & 0xFFFFu];
                    const float4 b = st[pk3 >> 16];
                    p0.x *= a.x; p0.y *= a.y; p0.z *= a.z; p0.w *= a.w;
                    p1.x *= b.x; p1.y *= b.y; p1.z *= b.z; p1.w *= b.w;
                }
                {
                    const float4 a = st[pk4 & 0xFFFFu];
                    const float4 b = st[pk4 >> 16];
                    p0.x *= a.x; p0.y *= a.y; p0.z *= a.z; p0.w *= a.w;
                    p1.x *= b.x; p1.y *= b.y; p1.z *= b.z; p1.w *= b.w;
                }
                float4 p;
                p.x = p0.x * p1.x;  p.y = p0.y * p1.y;
                p.z = p0.z * p1.z;  p.w = p0.w * p1.w;

                float4 cm;
                cm.x = fast_2atanh(p.x);
                cm.y = fast_2atanh(p.y);
                cm.z = fast_2atanh(p.z);
                cm.w = fast_2atanh(p.w);

                const float4 c = cur[i];
                if (it < ITERS - 1) g_P[g][n] = c;     // dead on last iteration

                float4 nv;
                nv.x = wl.x + cm.x + w0 * c.x + w1 * pr.x;
                nv.y = wl.y + cm.y + w0 * c.y + w1 * pr.y;
                nv.z = wl.z + cm.z + w0 * c.z + w1 * pr.z;
                nv.w = wl.w + cm.w + w0 * c.w + w1 * pr.w;
                cur[i] = nv;
            }
        }
        __syncthreads();   // protect st before next iteration's Phase A
    }

    // Epilogue: soft_bits = sigmoid(vm + input_llr), 4 coalesced row streams.
    #pragma unroll
    for (int i = 0; i < NPTMAX; i++) {
        const int n = tid + i * TPB;
        if (n < NODES) {
            const float4 c = cur[i];
            float* o = out + (size_t)row0 * NODES;
            o[n]             = fast_sigmoid(c.x + llr0[n]);
            o[NODES + n]     = fast_sigmoid(c.y + llr0[NODES + n]);
            o[2 * NODES + n] = fast_sigmoid(c.z + llr0[2 * NODES + n]);
            o[3 * NODES + n] = fast_sigmoid(c.w + llr0[3 * NODES + n]);
        }
    }
}

// ---------------------------------------------------------------------------
extern "C" void kernel_launch(void* const* d_in, const int* in_sizes, int n_in,
                              void* d_out, int out_size)
{
    const float* input_llr = (const float*)d_in[0];
    const float* w_ch      = (const float*)d_in[1];
    const float* w_res     = (const float*)d_in[2];
    const int*   check_idx = (const int*)d_in[3];
    // d_in[4] (var_index_tensor) is unused by the reference computation.
    float* out = (float*)d_out;

    // one warp per group: NQG * 32 threads
    prep_sched_kernel<<<(NQG * 32 + 255) / 256, 256>>>(check_idx);

    cudaFuncSetAttribute(ldpc4_kernel,
                         cudaFuncAttributeMaxDynamicSharedMemorySize, SMEM_BYTES);
    ldpc4_kernel<<<NGROUPS, TPB, SMEM_BYTES>>>(input_llr, w_ch, w_res, out);
}

// round 12
// speedup vs baseline: 1.0109x; 1.0109x over previous
#include <cuda_runtime.h>

#define NODES  8448
#define NB     10
#define ITERS  5
#define TPB    768
#define NPT    11            // 768 * 11 = 8448 (exact; no guards)
#define NBATCH 1024
#define RPC    2             // batch rows per CTA (packed as float2)
#define NGROUPS (NBATCH / RPC)   // 512
#define NQG16  (NODES / 16)  // 528 half-warp node groups (LDS.64 phase = 16 lanes)

#define SMEM_BYTES (NODES * 8)   // float2 tanh table = 67584 B (2 CTAs/SM)

// Global scratch (static __device__ arrays; no allocation).
__device__ unsigned int g_pk[5][NODES];       // u16 neighbor ids, 2-per-u32, slot-SoA
__device__ float2       g_wllr[NGROUPS][NODES];
__device__ float2       g_P[NGROUPS][NODES];  // vm_{t-1}

// ---------------------------------------------------------------------------
// Prep: for each aligned group of 16 nodes (one LDS.64 half-warp phase),
// permute each node's 10 neighbor indices among the 10 gather slots so that,
// per slot, the 16 lanes' bank-groups (idx % 16 for 8-byte words) are as
// distinct as possible. Product is commutative -> any permutation is exact.
//
// ONE WARP PER GROUP (same REDUX machinery as the winning R10 prep, widened to
// 16 bank-groups: counters are 16 x 4-bit nibbles split across two u32).
__global__ void prep_sched_kernel(const int* __restrict__ check_idx)
{
    const int warp = (blockIdx.x * blockDim.x + threadIdx.x) >> 5;
    const int lane = threadIdx.x & 31;
    if (warp >= NQG16) return;

    const int base = warp * 160;         // 16 nodes * 10 indices
    unsigned v0 = (unsigned)check_idx[base + lane];
    unsigned v1 = (unsigned)check_idx[base + 32 + lane];
    unsigned v2 = (unsigned)check_idx[base + 64 + lane];
    unsigned v3 = (unsigned)check_idx[base + 96 + lane];
    unsigned v4 = (unsigned)check_idx[base + 128 + lane];

    const bool is_slot = (lane < 10);
    unsigned clo = 0u, chi = 0u;         // my slot's 16 nibble bank-group counts

    #pragma unroll
    for (int ln = 0; ln < 16; ln++) {
        unsigned taken = 0u;
        unsigned perm  = 0u;

        #pragma unroll
        for (int j = 0; j < 10; j++) {
            const int flat = ln * 10 + j;          // compile-time constant
            unsigned v;
            if      (flat < 32)  v = __shfl_sync(0xFFFFFFFFu, v0, flat);
            else if (flat < 64)  v = __shfl_sync(0xFFFFFFFFu, v1, flat - 32);
            else if (flat < 96)  v = __shfl_sync(0xFFFFFFFFu, v2, flat - 64);
            else if (flat < 128) v = __shfl_sync(0xFFFFFFFFu, v3, flat - 96);
            else                 v = __shfl_sync(0xFFFFFFFFu, v4, flat - 128);

            const unsigned sh = (v & 15u) * 4u;    // nibble shift (0..60)
            const unsigned c  = ((sh < 32u) ? (clo >> sh) : (chi >> (sh - 32u))) & 0xFu;
            const unsigned key = (is_slot && !taken) ? ((c << 8) | (unsigned)lane)
                                                     : 0xFFFFu;
            const unsigned best = __reduce_min_sync(0xFFFFFFFFu, key) & 0xFFu;
            if ((unsigned)lane == best) {
                taken = 1u;
                if (sh < 32u) clo += 1u << sh; else chi += 1u << (sh - 32u);
                perm = v;
            }
        }
        // Threads 0..9 hold this node's permuted indices by slot; pack pairs.
        const unsigned plo = __shfl_sync(0xFFFFFFFFu, perm, (lane << 1), 32);
        const unsigned phi = __shfl_sync(0xFFFFFFFFu, perm, (lane << 1) + 1, 32);
        if (lane < 5)
            g_pk[lane][warp * 16 + ln] = (plo & 0xFFFFu) | (phi << 16);
    }
}

// ---------------------------------------------------------------------------
__global__ __launch_bounds__(TPB, 2)     // TWO independent CTAs per SM
void ldpc2_kernel(const float* __restrict__ input_llr,
                  const float* __restrict__ w_ch,
                  const float* __restrict__ w_res,   // (2, NODES)
                  float*       __restrict__ out)
{
    extern __shared__ float2 st[];                   // tanh values, 2 rows packed
    const int tid  = threadIdx.x;
    const int g    = blockIdx.x;
    const int row0 = g * RPC;
    const float* llr0 = input_llr + (size_t)row0 * NODES;

    float2 cur[NPT];   // current var_messages for this thread's nodes (2 rows)

    // Prologue: weighted LLR -> registers + global scratch.
    #pragma unroll
    for (int i = 0; i < NPT; i++) {
        const int n = tid + i * TPB;
        const float wc = w_ch[n];
        float2 wl;
        wl.x = llr0[n]         * wc;
        wl.y = llr0[NODES + n] * wc;
        g_wllr[g][n] = wl;
        cur[i] = wl;
    }

    for (int it = 0; it < ITERS; it++) {
        // Phase A: publish t = tanh(clip(0.5 * vm)) for 2 rows (one STS.64).
        #pragma unroll
        for (int i = 0; i < NPT; i++) {
            const int n = tid + i * TPB;
            const float2 v = cur[i];
            float2 t;
            t.x = tanhf(fminf(9.9f, fmaxf(-9.9f, 0.5f * v.x)));
            t.y = tanhf(fminf(9.9f, fmaxf(-9.9f, 0.5f * v.y)));
            st[n] = t;
        }
        __syncthreads();

        // Phase B: gather 10 scheduled neighbors (LDS.64 serves 2 rows),
        // product, 2*atanh, residual, update.
        #pragma unroll 1     // contain register pressure under the 2-CTA cap
        for (int i = 0; i < NPT; i++) {
            const int n = tid + i * TPB;
            const unsigned pk0 = g_pk[0][n], pk1 = g_pk[1][n];
            const unsigned pk2 = g_pk[2][n], pk3 = g_pk[3][n];
            const unsigned pk4 = g_pk[4][n];

            // prefetch iteration-state (L2 latency overlaps LDS work)
            float2 pr = make_float2(0.f, 0.f);
            if (it > 0) pr = g_P[g][n];
            const float2 wl = g_wllr[g][n];
            const float  w0 = w_res[n];
            const float  w1 = w_res[NODES + n];

            float2 p0 = st[pk0 & 0xFFFFu];
            float2 p1 = st[pk0 >> 16];
            {
                const float2 a = st[pk1 & 0xFFFFu];
                const float2 b = st[pk1 >> 16];
                p0.x *= a.x; p0.y *= a.y;
                p1.x *= b.x; p1.y *= b.y;
            }
            {
                const float2 a = st[pk2 & 0xFFFFu];
                const float2 b = st[pk2 >> 16];
                p0.x *= a.x; p0.y *= a.y;
                p1.x *= b.x; p1.y *= b.y;
            }
            {
                const float2 a = st[pk3 & 0xFFFFu];
                const float2 b = st[pk3 >> 16];
                p0.x *= a.x; p0.y *= a.y;
                p1.x *= b.x; p1.y *= b.y;
            }
            {
                const float2 a = st[pk4 & 0xFFFFu];
                const float2 b = st[pk4 >> 16];
                p0.x *= a.x; p0.y *= a.y;
                p1.x *= b.x; p1.y *= b.y;
            }
            float2 p;
            p.x = p0.x * p1.x;
            p.y = p0.y * p1.y;

            p.x = fminf(0.999999f, fmaxf(-0.999999f, p.x));
            p.y = fminf(0.999999f, fmaxf(-0.999999f, p.y));
            float2 cm;
            cm.x = logf((1.0f + p.x) / (1.0f - p.x));   // 2*atanh(p)
            cm.y = logf((1.0f + p.y) / (1.0f - p.y));

            const float2 c = cur[i];
            if (it < ITERS - 1) g_P[g][n] = c;          // dead on last iteration

            float2 nv;
            nv.x = wl.x + cm.x + w0 * c.x + w1 * pr.x;
            nv.y = wl.y + cm.y + w0 * c.y + w1 * pr.y;
            cur[i] = nv;
        }
        __syncthreads();   // protect st before next iteration's Phase A
    }

    // Epilogue: soft_bits = sigmoid(vm + input_llr), 2 coalesced row streams.
    #pragma unroll
    for (int i = 0; i < NPT; i++) {
        const int n = tid + i * TPB;
        const float2 c = cur[i];
        float* o = out + (size_t)row0 * NODES;
        const float zx = c.x + llr0[n];
        const float zy = c.y + llr0[NODES + n];
        o[n]         = 1.0f / (1.0f + expf(-zx));
        o[NODES + n] = 1.0f / (1.0f + expf(-zy));
    }
}

// ---------------------------------------------------------------------------
extern "C" void kernel_launch(void* const* d_in, const int* in_sizes, int n_in,
                              void* d_out, int out_size)
{
    const float* input_llr = (const float*)d_in[0];
    const float* w_ch      = (const float*)d_in[1];
    const float* w_res     = (const float*)d_in[2];
    const int*   check_idx = (const int*)d_in[3];
    // d_in[4] (var_index_tensor) is unused by the reference computation.
    float* out = (float*)d_out;

    // one warp per 16-node group: NQG16 * 32 threads
    prep_sched_kernel<<<(NQG16 * 32 + 255) / 256, 256>>>(check_idx);

    cudaFuncSetAttribute(ldpc2_kernel,
                         cudaFuncAttributeMaxDynamicSharedMemorySize, SMEM_BYTES);
    ldpc2_kernel<<<NGROUPS, TPB, SMEM_BYTES>>>(input_llr, w_ch, w_res, out);
}

// round 13
// speedup vs baseline: 1.1183x; 1.1062x over previous
#include <cuda_runtime.h>

#define NODES  8448
#define NB     10
#define ITERS  5
#define TPB    1024
#define NPTMAX 9             // ceil(8448/1024); threads 0..255 do 9, rest do 8
#define NBATCH 1024
#define RPC    4             // batch rows per CTA (packed as float4)
#define NGROUPS (NBATCH / RPC)   // 256
#define NQG    (NODES / 8)   // 1056 quarter-warp node groups

#define SMEM_BYTES (NODES * 16)  // float4 tanh table = 135168 B

// Global scratch (static __device__ arrays; no allocation).
__device__ unsigned int g_pk[5][NODES];       // u16 neighbor ids, 2-per-u32, slot-SoA
__device__ float2       g_wr[NODES];          // packed (w_res[0][n], w_res[1][n])
__device__ float4       g_wllr[NGROUPS][NODES];
__device__ float4       g_P[NGROUPS][NODES];  // vm_{t-1}

// ---------------------------------------------------------------------------
// Prep: one warp per 8-node group; threads 0..9 own slot counters; argmin over
// slots via a single __reduce_min_sync. Bit-identical schedule to R7 greedy.
// Also packs w_res rows into float2 (exact).
__global__ void prep_sched_kernel(const int* __restrict__ check_idx,
                                  const float* __restrict__ w_res)
{
    const int warp = (blockIdx.x * blockDim.x + threadIdx.x) >> 5;
    const int lane = threadIdx.x & 31;
    if (warp >= NQG) return;

    const int base = warp * 80;          // 8 nodes * 10 indices
    const unsigned v0 = (unsigned)check_idx[base + lane];
    const unsigned v1 = (unsigned)check_idx[base + 32 + lane];
    const unsigned v2 = (lane < 16) ? (unsigned)check_idx[base + 64 + lane] : 0u;

    // pack residual weights for this warp's 8 nodes
    if (lane < 8) {
        const int n = warp * 8 + lane;
        g_wr[n] = make_float2(w_res[n], w_res[NODES + n]);
    }

    const bool is_slot = (lane < 10);
    unsigned cnt = 0u;                   // my slot's 8 nibble bank-group counts

    #pragma unroll
    for (int ln = 0; ln < 8; ln++) {
        unsigned taken = 0u;
        unsigned perm  = 0u;

        #pragma unroll
        for (int j = 0; j < 10; j++) {
            const int flat = ln * 10 + j;          // compile-time constant
            unsigned v;
            if      (flat < 32) v = __shfl_sync(0xFFFFFFFFu, v0, flat);
            else if (flat < 64) v = __shfl_sync(0xFFFFFFFFu, v1, flat - 32);
            else                v = __shfl_sync(0xFFFFFFFFu, v2, flat - 64);

            const unsigned sh = (v & 7u) * 4u;
            const unsigned c  = (cnt >> sh) & 0xFu;
            const unsigned key = (is_slot && !taken) ? ((c << 8) | (unsigned)lane)
                                                     : 0xFFFFu;
            const unsigned best = __reduce_min_sync(0xFFFFFFFFu, key) & 0xFFu;
            if ((unsigned)lane == best) {
                taken = 1u;
                cnt  += 1u << sh;
                perm  = v;
            }
        }
        const unsigned plo = __shfl_sync(0xFFFFFFFFu, perm, (lane << 1), 32);
        const unsigned phi = __shfl_sync(0xFFFFFFFFu, perm, (lane << 1) + 1, 32);
        if (lane < 5)
            g_pk[lane][warp * 8 + ln] = (plo & 0xFFFFu) | (phi << 16);
    }
}

// ---------------------------------------------------------------------------
__global__ __launch_bounds__(TPB, 1)
void ldpc4_kernel(const float* __restrict__ input_llr,
                  const float* __restrict__ w_ch,
                  float*       __restrict__ out)
{
    extern __shared__ float4 st[];                   // tanh values, 4 rows packed
    const int tid  = threadIdx.x;
    const int g    = blockIdx.x;
    const int row0 = g * RPC;
    const float* llr0 = input_llr + (size_t)row0 * NODES;

    float4 cur[NPTMAX];   // current var_messages for this thread's nodes (4 rows)

    // Prologue: weighted LLR -> registers + global scratch.
    #pragma unroll
    for (int i = 0; i < NPTMAX; i++) {
        const int n = tid + i * TPB;
        if (n < NODES) {
            const float wc = w_ch[n];
            float4 wl;
            wl.x = llr0[n]             * wc;
            wl.y = llr0[NODES + n]     * wc;
            wl.z = llr0[2 * NODES + n] * wc;
            wl.w = llr0[3 * NODES + n] * wc;
            g_wllr[g][n] = wl;
            cur[i] = wl;
        }
    }

    for (int it = 0; it < ITERS; it++) {
        // Phase A: publish t = tanh(0.5 * vm) for all 4 rows (one STS.128).
        // NOTE: the reference's clip(0.5v, -9.9, 9.9) is a provable no-op in
        // fp32 (tanh rounds to 1.0f for |x| >= ~8.32, and the clip is inactive
        // below 9.9), so it is dropped — bit-identical result.
        #pragma unroll
        for (int i = 0; i < NPTMAX; i++) {
            const int n = tid + i * TPB;
            if (n < NODES) {
                const float4 v = cur[i];
                float4 t;
                t.x = tanhf(0.5f * v.x);
                t.y = tanhf(0.5f * v.y);
                t.z = tanhf(0.5f * v.z);
                t.w = tanhf(0.5f * v.w);
                st[n] = t;
            }
        }
        __syncthreads();

        // Phase B: gather 10 scheduled neighbors (LDS.128 serves 4 rows),
        // product, 2*atanh, residual, update.
        #pragma unroll 2
        for (int i = 0; i < NPTMAX; i++) {
            const int n = tid + i * TPB;
            if (n < NODES) {
                const unsigned pk0 = g_pk[0][n], pk1 = g_pk[1][n];
                const unsigned pk2 = g_pk[2][n], pk3 = g_pk[3][n];
                const unsigned pk4 = g_pk[4][n];

                // prefetch iteration-state (L2 latency overlaps LDS work)
                float4 pr = make_float4(0.f, 0.f, 0.f, 0.f);
                if (it > 0) pr = g_P[g][n];
                const float4 wl = g_wllr[g][n];
                const float2 wr = g_wr[n];

                float4 p0 = st[pk0 & 0xFFFFu];
                float4 p1 = st[pk0 >> 16];
                {
                    const float4 a = st[pk1 & 0xFFFFu];
                    const float4 b = st[pk1 >> 16];
                    p0.x *= a.x; p0.y *= a.y; p0.z *= a.z; p0.w *= a.w;
                    p1.x *= b.x; p1.y *= b.y; p1.z *= b.z; p1.w *= b.w;
                }
                {
                    const float4 a = st[pk2 & 0xFFFFu];
                    const float4 b = st[pk2 >> 16];
                    p0.x *= a.x; p0.y *= a.y; p0.z *= a.z; p0.w *= a.w;
                    p1.x *= b.x; p1.y *= b.y; p1.z *= b.z; p1.w *= b.w;
                }
                {
                    const float4 a = st[pk3 & 0xFFFFu];
                    const float4 b = st[pk3 >> 16];
                    p0.x *= a.x; p0.y *= a.y; p0.z *= a.z; p0.w *= a.w;
                    p1.x *= b.x; p1.y *= b.y; p1.z *= b.z; p1.w *= b.w;
                }
                {
                    const float4 a = st[pk4 & 0xFFFFu];
                    const float4 b = st[pk4 >> 16];
                    p0.x *= a.x; p0.y *= a.y; p0.z *= a.z; p0.w *= a.w;
                    p1.x *= b.x; p1.y *= b.y; p1.z *= b.z; p1.w *= b.w;
                }
                float4 p;
                p.x = p0.x * p1.x;  p.y = p0.y * p1.y;
                p.z = p0.z * p1.z;  p.w = p0.w * p1.w;

                p.x = fminf(0.999999f, fmaxf(-0.999999f, p.x));
                p.y = fminf(0.999999f, fmaxf(-0.999999f, p.y));
                p.z = fminf(0.999999f, fmaxf(-0.999999f, p.z));
                p.w = fminf(0.999999f, fmaxf(-0.999999f, p.w));
                float4 cm;
                cm.x = logf((1.0f + p.x) / (1.0f - p.x));   // 2*atanh(p)
                cm.y = logf((1.0f + p.y) / (1.0f - p.y));
                cm.z = logf((1.0f + p.z) / (1.0f - p.z));
                cm.w = logf((1.0f + p.w) / (1.0f - p.w));

                const float4 c = cur[i];
                if (it < ITERS - 1) g_P[g][n] = c;     // dead on last iteration

                float4 nv;
                nv.x = wl.x + cm.x + wr.x * c.x + wr.y * pr.x;
                nv.y = wl.y + cm.y + wr.x * c.y + wr.y * pr.y;
                nv.z = wl.z + cm.z + wr.x * c.z + wr.y * pr.z;
                nv.w = wl.w + cm.w + wr.x * c.w + wr.y * pr.w;
                cur[i] = nv;
            }
        }
        __syncthreads();   // protect st before next iteration's Phase A
    }

    // Epilogue: soft_bits = sigmoid(vm + input_llr), 4 coalesced row streams.
    #pragma unroll
    for (int i = 0; i < NPTMAX; i++) {
        const int n = tid + i * TPB;
        if (n < NODES) {
            const float4 c = cur[i];
            float* o = out + (size_t)row0 * NODES;
            const float zx = c.x + llr0[n];
            const float zy = c.y + llr0[NODES + n];
            const float zz = c.z + llr0[2 * NODES + n];
            const float zw = c.w + llr0[3 * NODES + n];
            o[n]             = 1.0f / (1.0f + expf(-zx));
            o[NODES + n]     = 1.0f / (1.0f + expf(-zy));
            o[2 * NODES + n] = 1.0f / (1.0f + expf(-zz));
            o[3 * NODES + n] = 1.0f / (1.0f + expf(-zw));
        }
    }
}

// ---------------------------------------------------------------------------
extern "C" void kernel_launch(void* const* d_in, const int* in_sizes, int n_in,
                              void* d_out, int out_size)
{
    const float* input_llr = (const float*)d_in[0];
    const float* w_ch      = (const float*)d_in[1];
    const float* w_res     = (const float*)d_in[2];
    const int*   check_idx = (const int*)d_in[3];
    // d_in[4] (var_index_tensor) is unused by the reference computation.
    float* out = (float*)d_out;

    // one warp per group: NQG * 32 threads
    prep_sched_kernel<<<(NQG * 32 + 255) / 256, 256>>>(check_idx, w_res);

    cudaFuncSetAttribute(ldpc4_kernel,
                         cudaFuncAttributeMaxDynamicSharedMemorySize, SMEM_BYTES);
    ldpc4_kernel<<<NGROUPS, TPB, SMEM_BYTES>>>(input_llr, w_ch, out);
}

// round 14
// speedup vs baseline: 1.1521x; 1.0302x over previous
#include <cuda_runtime.h>

#define NODES  8448
#define NB     10
#define ITERS  5
#define TPB    1024
#define NPTMAX 9             // ceil(8448/1024); threads 0..255 do 9, rest do 8
#define NBATCH 1024
#define RPC    4             // batch rows per CTA (packed as float4)
#define NGROUPS (NBATCH / RPC)   // 256
#define NQG    (NODES / 8)   // 1056 quarter-warp node groups

#define SMEM_BYTES (NODES * 16)  // float4 tanh table = 135168 B

// Global scratch (static __device__ arrays; no allocation).
__device__ uint4        g_pk4[NODES];         // neighbor pairs, slots 0..7 (AoS)
__device__ unsigned int g_pk1[NODES];         // neighbor pair, slots 8..9
__device__ float2       g_wr[NODES];          // packed (w_res[0][n], w_res[1][n])
__device__ float4       g_wllr[NGROUPS][NODES];
__device__ float4       g_P[NGROUPS][NODES];  // vm_{t-1}

// ---------------------------------------------------------------------------
// Prep: one warp per 8-node group; threads 0..9 own slot counters; argmin over
// slots via a single __reduce_min_sync. Bit-identical schedule to R7 greedy.
// Packs w_res into float2 and the permuted neighbor pairs into AoS uint4+u32.
__global__ void prep_sched_kernel(const int* __restrict__ check_idx,
                                  const float* __restrict__ w_res)
{
    const int warp = (blockIdx.x * blockDim.x + threadIdx.x) >> 5;
    const int lane = threadIdx.x & 31;
    if (warp >= NQG) return;

    const int base = warp * 80;          // 8 nodes * 10 indices
    const unsigned v0 = (unsigned)check_idx[base + lane];
    const unsigned v1 = (unsigned)check_idx[base + 32 + lane];
    const unsigned v2 = (lane < 16) ? (unsigned)check_idx[base + 64 + lane] : 0u;

    // pack residual weights for this warp's 8 nodes
    if (lane < 8) {
        const int n = warp * 8 + lane;
        g_wr[n] = make_float2(w_res[n], w_res[NODES + n]);
    }

    const bool is_slot = (lane < 10);
    unsigned cnt = 0u;                   // my slot's 8 nibble bank-group counts

    #pragma unroll
    for (int ln = 0; ln < 8; ln++) {
        unsigned taken = 0u;
        unsigned perm  = 0u;

        #pragma unroll
        for (int j = 0; j < 10; j++) {
            const int flat = ln * 10 + j;          // compile-time constant
            unsigned v;
            if      (flat < 32) v = __shfl_sync(0xFFFFFFFFu, v0, flat);
            else if (flat < 64) v = __shfl_sync(0xFFFFFFFFu, v1, flat - 32);
            else                v = __shfl_sync(0xFFFFFFFFu, v2, flat - 64);

            const unsigned sh = (v & 7u) * 4u;
            const unsigned c  = (cnt >> sh) & 0xFu;
            const unsigned key = (is_slot && !taken) ? ((c << 8) | (unsigned)lane)
                                                     : 0xFFFFu;
            const unsigned best = __reduce_min_sync(0xFFFFFFFFu, key) & 0xFFu;
            if ((unsigned)lane == best) {
                taken = 1u;
                cnt  += 1u << sh;
                perm  = v;
            }
        }
        // lanes 0..4 hold this node's slot-pairs; collect to lane 0, AoS write
        const unsigned plo = __shfl_sync(0xFFFFFFFFu, perm, (lane << 1), 32);
        const unsigned phi = __shfl_sync(0xFFFFFFFFu, perm, (lane << 1) + 1, 32);
        const unsigned pr  = (plo & 0xFFFFu) | (phi << 16);
        const unsigned q1 = __shfl_sync(0xFFFFFFFFu, pr, 1);
        const unsigned q2 = __shfl_sync(0xFFFFFFFFu, pr, 2);
        const unsigned q3 = __shfl_sync(0xFFFFFFFFu, pr, 3);
        const unsigned q4 = __shfl_sync(0xFFFFFFFFu, pr, 4);
        if (lane == 0) {
            const int n = warp * 8 + ln;
            g_pk4[n] = make_uint4(pr, q1, q2, q3);
            g_pk1[n] = q4;
        }
    }
}

// ---------------------------------------------------------------------------
// Fast 2*atanh (MUFU rcp+lg2; rel err ~3e-6 — proven to pass in R3/R11).
__device__ __forceinline__ float fast_2atanh(float p)
{
    p = fminf(0.999999f, fmaxf(-0.999999f, p));
    return __logf(__fdividef(1.0f + p, 1.0f - p));
}

// ---------------------------------------------------------------------------
__global__ __launch_bounds__(TPB, 1)
void ldpc4_kernel(const float* __restrict__ input_llr,
                  const float* __restrict__ w_ch,
                  float*       __restrict__ out)
{
    extern __shared__ float4 st[];                   // tanh values, 4 rows packed
    const int tid  = threadIdx.x;
    const int g    = blockIdx.x;
    const int row0 = g * RPC;
    const float* llr0 = input_llr + (size_t)row0 * NODES;

    float4 cur[NPTMAX];   // current var_messages for this thread's nodes (4 rows)

    // Prologue: weighted LLR -> registers + global scratch.
    #pragma unroll
    for (int i = 0; i < NPTMAX; i++) {
        const int n = tid + i * TPB;
        if (n < NODES) {
            const float wc = w_ch[n];
            float4 wl;
            wl.x = llr0[n]             * wc;
            wl.y = llr0[NODES + n]     * wc;
            wl.z = llr0[2 * NODES + n] * wc;
            wl.w = llr0[3 * NODES + n] * wc;
            g_wllr[g][n] = wl;
            cur[i] = wl;
        }
    }

    for (int it = 0; it < ITERS; it++) {
        // Phase A: publish t = tanh(0.5 * vm) for all 4 rows (one STS.128).
        // (reference's clip is a provable fp32 no-op — see R13)
        #pragma unroll
        for (int i = 0; i < NPTMAX; i++) {
            const int n = tid + i * TPB;
            if (n < NODES) {
                const float4 v = cur[i];
                float4 t;
                t.x = tanhf(0.5f * v.x);
                t.y = tanhf(0.5f * v.y);
                t.z = tanhf(0.5f * v.z);
                t.w = tanhf(0.5f * v.w);
                st[n] = t;
            }
        }
        __syncthreads();

        // Phase B: gather 10 scheduled neighbors (LDS.128 serves 4 rows),
        // product, 2*atanh, residual, update.
        #pragma unroll 2
        for (int i = 0; i < NPTMAX; i++) {
            const int n = tid + i * TPB;
            if (n < NODES) {
                const uint4    pka = g_pk4[n];
                const unsigned pk4v = g_pk1[n];

                // prefetch iteration-state (L2 latency overlaps LDS work)
                float4 pr = make_float4(0.f, 0.f, 0.f, 0.f);
                if (it > 0) pr = g_P[g][n];
                const float4 wl = g_wllr[g][n];
                const float2 wr = g_wr[n];

                float4 p0 = st[pka.x & 0xFFFFu];
                float4 p1 = st[pka.x >> 16];
                {
                    const float4 a = st[pka.y & 0xFFFFu];
                    const float4 b = st[pka.y >> 16];
                    p0.x *= a.x; p0.y *= a.y; p0.z *= a.z; p0.w *= a.w;
                    p1.x *= b.x; p1.y *= b.y; p1.z *= b.z; p1.w *= b.w;
                }
                {
                    const float4 a = st[pka.z & 0xFFFFu];
                    const float4 b = st[pka.z >> 16];
                    p0.x *= a.x; p0.y *= a.y; p0.z *= a.z; p0.w *= a.w;
                    p1.x *= b.x; p1.y *= b.y; p1.z *= b.z; p1.w *= b.w;
                }
                {
                    const float4 a = st[pka.w & 0xFFFFu];
                    const float4 b = st[pka.w >> 16];
                    p0.x *= a.x; p0.y *= a.y; p0.z *= a.z; p0.w *= a.w;
                    p1.x *= b.x; p1.y *= b.y; p1.z *= b.z; p1.w *= b.w;
                }
                {
                    const float4 a = st[pk4v & 0xFFFFu];
                    const float4 b = st[pk4v >> 16];
                    p0.x *= a.x; p0.y *= a.y; p0.z *= a.z; p0.w *= a.w;
                    p1.x *= b.x; p1.y *= b.y; p1.z *= b.z; p1.w *= b.w;
                }
                float4 p;
                p.x = p0.x * p1.x;  p.y = p0.y * p1.y;
                p.z = p0.z * p1.z;  p.w = p0.w * p1.w;

                float4 cm;
                cm.x = fast_2atanh(p.x);
                cm.y = fast_2atanh(p.y);
                cm.z = fast_2atanh(p.z);
                cm.w = fast_2atanh(p.w);

                const float4 c = cur[i];
                if (it < ITERS - 1) g_P[g][n] = c;     // dead on last iteration

                float4 nv;
                nv.x = wl.x + cm.x + wr.x * c.x + wr.y * pr.x;
                nv.y = wl.y + cm.y + wr.x * c.y + wr.y * pr.y;
                nv.z = wl.z + cm.z + wr.x * c.z + wr.y * pr.z;
                nv.w = wl.w + cm.w + wr.x * c.w + wr.y * pr.w;
                cur[i] = nv;
            }
        }
        __syncthreads();   // protect st before next iteration's Phase A
    }

    // Epilogue: soft_bits = sigmoid(vm + input_llr), 4 coalesced row streams.
    #pragma unroll
    for (int i = 0; i < NPTMAX; i++) {
        const int n = tid + i * TPB;
        if (n < NODES) {
            const float4 c = cur[i];
            float* o = out + (size_t)row0 * NODES;
            const float zx = c.x + llr0[n];
            const float zy = c.y + llr0[NODES + n];
            const float zz = c.z + llr0[2 * NODES + n];
            const float zw = c.w + llr0[3 * NODES + n];
            o[n]             = 1.0f / (1.0f + expf(-zx));
            o[NODES + n]     = 1.0f / (1.0f + expf(-zy));
            o[2 * NODES + n] = 1.0f / (1.0f + expf(-zz));
            o[3 * NODES + n] = 1.0f / (1.0f + expf(-zw));
        }
    }
}

// ---------------------------------------------------------------------------
extern "C" void kernel_launch(void* const* d_in, const int* in_sizes, int n_in,
                              void* d_out, int out_size)
{
    const float* input_llr = (const float*)d_in[0];
    const float* w_ch      = (const float*)d_in[1];
    const float* w_res     = (const float*)d_in[2];
    const int*   check_idx = (const int*)d_in[3];
    // d_in[4] (var_index_tensor) is unused by the reference computation.
    float* out = (float*)d_out;

    // one warp per group: NQG * 32 threads
    prep_sched_kernel<<<(NQG * 32 + 255) / 256, 256>>>(check_idx, w_res);

    cudaFuncSetAttribute(ldpc4_kernel,
                         cudaFuncAttributeMaxDynamicSharedMemorySize, SMEM_BYTES);
    ldpc4_kernel<<<NGROUPS, TPB, SMEM_BYTES>>>(input_llr, w_ch, out);
}

// round 15
// speedup vs baseline: 1.1875x; 1.0307x over previous
#include <cuda_runtime.h>

#define NODES  8448
#define NB     10
#define ITERS  5
#define TPB    768
#define NPT    11            // 768 * 11 = 8448 exact — no guards, no tail
#define NBATCH 1024
#define RPC    4             // batch rows per CTA (packed as float4)
#define NGROUPS (NBATCH / RPC)   // 256
#define NQG    (NODES / 8)   // 1056 quarter-warp node groups

#define SMEM_BYTES (NODES * 16)  // float4 tanh table = 135168 B

// Global scratch (static __device__ arrays; no allocation).
__device__ uint4        g_pk4[NODES];         // neighbor pairs, slots 0..7 (AoS)
__device__ unsigned int g_pk1[NODES];         // neighbor pair, slots 8..9
__device__ float2       g_wr[NODES];          // packed (w_res[0][n], w_res[1][n])
__device__ float4       g_wllr[NGROUPS][NODES];
__device__ float4       g_P[NGROUPS][NODES];  // vm_{t-1}

// ---------------------------------------------------------------------------
// Prep: one warp per 8-node group; threads 0..9 own slot counters; argmin over
// slots via a single __reduce_min_sync. Bit-identical schedule to R7 greedy.
// Packs w_res into float2 and the permuted neighbor pairs into AoS uint4+u32.
__global__ void prep_sched_kernel(const int* __restrict__ check_idx,
                                  const float* __restrict__ w_res)
{
    const int warp = (blockIdx.x * blockDim.x + threadIdx.x) >> 5;
    const int lane = threadIdx.x & 31;
    if (warp >= NQG) return;

    const int base = warp * 80;          // 8 nodes * 10 indices
    const unsigned v0 = (unsigned)check_idx[base + lane];
    const unsigned v1 = (unsigned)check_idx[base + 32 + lane];
    const unsigned v2 = (lane < 16) ? (unsigned)check_idx[base + 64 + lane] : 0u;

    // pack residual weights for this warp's 8 nodes
    if (lane < 8) {
        const int n = warp * 8 + lane;
        g_wr[n] = make_float2(w_res[n], w_res[NODES + n]);
    }

    const bool is_slot = (lane < 10);
    unsigned cnt = 0u;                   // my slot's 8 nibble bank-group counts

    #pragma unroll
    for (int ln = 0; ln < 8; ln++) {
        unsigned taken = 0u;
        unsigned perm  = 0u;

        #pragma unroll
        for (int j = 0; j < 10; j++) {
            const int flat = ln * 10 + j;          // compile-time constant
            unsigned v;
            if      (flat < 32) v = __shfl_sync(0xFFFFFFFFu, v0, flat);
            else if (flat < 64) v = __shfl_sync(0xFFFFFFFFu, v1, flat - 32);
            else                v = __shfl_sync(0xFFFFFFFFu, v2, flat - 64);

            const unsigned sh = (v & 7u) * 4u;
            const unsigned c  = (cnt >> sh) & 0xFu;
            const unsigned key = (is_slot && !taken) ? ((c << 8) | (unsigned)lane)
                                                     : 0xFFFFu;
            const unsigned best = __reduce_min_sync(0xFFFFFFFFu, key) & 0xFFu;
            if ((unsigned)lane == best) {
                taken = 1u;
                cnt  += 1u << sh;
                perm  = v;
            }
        }
        // lanes 0..4 hold this node's slot-pairs; collect to lane 0, AoS write
        const unsigned plo = __shfl_sync(0xFFFFFFFFu, perm, (lane << 1), 32);
        const unsigned phi = __shfl_sync(0xFFFFFFFFu, perm, (lane << 1) + 1, 32);
        const unsigned pr  = (plo & 0xFFFFu) | (phi << 16);
        const unsigned q1 = __shfl_sync(0xFFFFFFFFu, pr, 1);
        const unsigned q2 = __shfl_sync(0xFFFFFFFFu, pr, 2);
        const unsigned q3 = __shfl_sync(0xFFFFFFFFu, pr, 3);
        const unsigned q4 = __shfl_sync(0xFFFFFFFFu, pr, 4);
        if (lane == 0) {
            const int n = warp * 8 + ln;
            g_pk4[n] = make_uint4(pr, q1, q2, q3);
            g_pk1[n] = q4;
        }
    }
}

// ---------------------------------------------------------------------------
// Fast 2*atanh (MUFU rcp+lg2; rel err ~3e-6 — proven in R14).
__device__ __forceinline__ float fast_2atanh(float p)
{
    p = fminf(0.999999f, fmaxf(-0.999999f, p));
    return __logf(__fdividef(1.0f + p, 1.0f - p));
}

// ---------------------------------------------------------------------------
__global__ __launch_bounds__(TPB, 1)
void ldpc4_kernel(const float* __restrict__ input_llr,
                  const float* __restrict__ w_ch,
                  float*       __restrict__ out)
{
    extern __shared__ float4 st[];                   // tanh values, 4 rows packed
    const int tid  = threadIdx.x;
    const int g    = blockIdx.x;
    const int row0 = g * RPC;
    const float* llr0 = input_llr + (size_t)row0 * NODES;

    float4 cur[NPT];   // current var_messages for this thread's nodes (4 rows)

    // Prologue: weighted LLR -> registers + global scratch.
    #pragma unroll
    for (int i = 0; i < NPT; i++) {
        const int n = tid + i * TPB;
        const float wc = w_ch[n];
        float4 wl;
        wl.x = llr0[n]             * wc;
        wl.y = llr0[NODES + n]     * wc;
        wl.z = llr0[2 * NODES + n] * wc;
        wl.w = llr0[3 * NODES + n] * wc;
        g_wllr[g][n] = wl;
        cur[i] = wl;
    }

    for (int it = 0; it < ITERS; it++) {
        // Phase A: publish t = tanh(0.5 * vm) for all 4 rows (one STS.128).
        // (reference's clip is a provable fp32 no-op — see R13)
        #pragma unroll
        for (int i = 0; i < NPT; i++) {
            const int n = tid + i * TPB;
            const float4 v = cur[i];
            float4 t;
            t.x = tanhf(0.5f * v.x);
            t.y = tanhf(0.5f * v.y);
            t.z = tanhf(0.5f * v.z);
            t.w = tanhf(0.5f * v.w);
            st[n] = t;
        }
        __syncthreads();

        // Phase B: gather 10 scheduled neighbors (LDS.128 serves 4 rows),
        // product, 2*atanh, residual, update.
        #pragma unroll 2
        for (int i = 0; i < NPT; i++) {
            const int n = tid + i * TPB;
            const uint4    pka  = g_pk4[n];
            const unsigned pk4v = g_pk1[n];

            // prefetch iteration-state (L2 latency overlaps LDS work)
            float4 pr = make_float4(0.f, 0.f, 0.f, 0.f);
            if (it > 0) pr = g_P[g][n];
            const float4 wl = g_wllr[g][n];
            const float2 wr = g_wr[n];

            float4 p0 = st[pka.x & 0xFFFFu];
            float4 p1 = st[pka.x >> 16];
            {
                const float4 a = st[pka.y & 0xFFFFu];
                const float4 b = st[pka.y >> 16];
                p0.x *= a.x; p0.y *= a.y; p0.z *= a.z; p0.w *= a.w;
                p1.x *= b.x; p1.y *= b.y; p1.z *= b.z; p1.w *= b.w;
            }
            {
                const float4 a = st[pka.z & 0xFFFFu];
                const float4 b = st[pka.z >> 16];
                p0.x *= a.x; p0.y *= a.y; p0.z *= a.z; p0.w *= a.w;
                p1.x *= b.x; p1.y *= b.y; p1.z *= b.z; p1.w *= b.w;
            }
            {
                const float4 a = st[pka.w & 0xFFFFu];
                const float4 b = st[pka.w >> 16];
                p0.x *= a.x; p0.y *= a.y; p0.z *= a.z; p0.w *= a.w;
                p1.x *= b.x; p1.y *= b.y; p1.z *= b.z; p1.w *= b.w;
            }
            {
                const float4 a = st[pk4v & 0xFFFFu];
                const float4 b = st[pk4v >> 16];
                p0.x *= a.x; p0.y *= a.y; p0.z *= a.z; p0.w *= a.w;
                p1.x *= b.x; p1.y *= b.y; p1.z *= b.z; p1.w *= b.w;
            }
            float4 p;
            p.x = p0.x * p1.x;  p.y = p0.y * p1.y;
            p.z = p0.z * p1.z;  p.w = p0.w * p1.w;

            float4 cm;
            cm.x = fast_2atanh(p.x);
            cm.y = fast_2atanh(p.y);
            cm.z = fast_2atanh(p.z);
            cm.w = fast_2atanh(p.w);

            const float4 c = cur[i];
            if (it < ITERS - 1) g_P[g][n] = c;     // dead on last iteration

            float4 nv;
            nv.x = wl.x + cm.x + wr.x * c.x + wr.y * pr.x;
            nv.y = wl.y + cm.y + wr.x * c.y + wr.y * pr.y;
            nv.z = wl.z + cm.z + wr.x * c.z + wr.y * pr.z;
            nv.w = wl.w + cm.w + wr.x * c.w + wr.y * pr.w;
            cur[i] = nv;
        }
        __syncthreads();   // protect st before next iteration's Phase A
    }

    // Epilogue: soft_bits = sigmoid(vm + input_llr), 4 coalesced row streams.
    #pragma unroll
    for (int i = 0; i < NPT; i++) {
        const int n = tid + i * TPB;
        const float4 c = cur[i];
        float* o = out + (size_t)row0 * NODES;
        const float zx = c.x + llr0[n];
        const float zy = c.y + llr0[NODES + n];
        const float zz = c.z + llr0[2 * NODES + n];
        const float zw = c.w + llr0[3 * NODES + n];
        o[n]             = 1.0f / (1.0f + expf(-zx));
        o[NODES + n]     = 1.0f / (1.0f + expf(-zy));
        o[2 * NODES + n] = 1.0f / (1.0f + expf(-zz));
        o[3 * NODES + n] = 1.0f / (1.0f + expf(-zw));
    }
}

// ---------------------------------------------------------------------------
extern "C" void kernel_launch(void* const* d_in, const int* in_sizes, int n_in,
                              void* d_out, int out_size)
{
    const float* input_llr = (const float*)d_in[0];
    const float* w_ch      = (const float*)d_in[1];
    const float* w_res     = (const float*)d_in[2];
    const int*   check_idx = (const int*)d_in[3];
    // d_in[4] (var_index_tensor) is unused by the reference computation.
    float* out = (float*)d_out;

    // one warp per group: NQG * 32 threads
    prep_sched_kernel<<<(NQG * 32 + 255) / 256, 256>>>(check_idx, w_res);

    cudaFuncSetAttribute(ldpc4_kernel,
                         cudaFuncAttributeMaxDynamicSharedMemorySize, SMEM_BYTES);
    ldpc4_kernel<<<NGROUPS, TPB, SMEM_BYTES>>>(input_llr, w_ch, out);
}

// round 16
// speedup vs baseline: 1.1901x; 1.0022x over previous
#include <cuda_runtime.h>

#define NODES  8448
#define NB     10
#define ITERS  5
#define TPB    768
#define NPT    11            // 768 * 11 = 8448 exact — no guards, no tail
#define NPTDB  7             // nodes i<7 (n<5376) are double-buffered
#define DBN    (NPTDB * TPB) // 5376
#define NBATCH 1024
#define RPC    4             // batch rows per CTA (packed as float4)
#define NGROUPS (NBATCH / RPC)   // 256
#define NQG    (NODES / 8)   // 1056 quarter-warp node groups

// float4 main table (8448) + float4 alt slots for DB nodes (5376) = 221184 B
#define SMEM_BYTES ((NODES + DBN) * 16)

// Global scratch (static __device__ arrays; no allocation).
__device__ uint4        g_pk4e[NODES];        // slots 0..7, even-parity offsets
__device__ unsigned int g_pk1e[NODES];        // slots 8..9, even-parity
__device__ uint4        g_pk4o[NODES];        // slots 0..7, odd-parity offsets
__device__ unsigned int g_pk1o[NODES];        // slots 8..9, odd-parity
__device__ float2       g_wr[NODES];          // packed (w_res[0][n], w_res[1][n])
__device__ float4       g_wllr[NGROUPS][NODES];
__device__ float4       g_P[NGROUPS][NODES];  // vm_{t-1}

// ---------------------------------------------------------------------------
// Prep: one warp per 8-node group; threads 0..9 own slot counters; argmin over
// slots via a single __reduce_min_sync (bit-identical schedule to R7 greedy).
// Emits TWO pre-resolved u16 index tables: even parity (all neighbors read the
// main table at offset idx) and odd parity (double-buffered neighbors idx<DBN
// read the alternate slot at offset idx+NODES). Also packs w_res into float2.
__global__ void prep_sched_kernel(const int* __restrict__ check_idx,
                                  const float* __restrict__ w_res)
{
    const int warp = (blockIdx.x * blockDim.x + threadIdx.x) >> 5;
    const int lane = threadIdx.x & 31;
    if (warp >= NQG) return;

    const int base = warp * 80;          // 8 nodes * 10 indices
    const unsigned v0 = (unsigned)check_idx[base + lane];
    const unsigned v1 = (unsigned)check_idx[base + 32 + lane];
    const unsigned v2 = (lane < 16) ? (unsigned)check_idx[base + 64 + lane] : 0u;

    if (lane < 8) {
        const int n = warp * 8 + lane;
        g_wr[n] = make_float2(w_res[n], w_res[NODES + n]);
    }

    const bool is_slot = (lane < 10);
    unsigned cnt = 0u;                   // my slot's 8 nibble bank-group counts

    #pragma unroll
    for (int ln = 0; ln < 8; ln++) {
        unsigned taken = 0u;
        unsigned perm  = 0u;

        #pragma unroll
        for (int j = 0; j < 10; j++) {
            const int flat = ln * 10 + j;          // compile-time constant
            unsigned v;
            if      (flat < 32) v = __shfl_sync(0xFFFFFFFFu, v0, flat);
            else if (flat < 64) v = __shfl_sync(0xFFFFFFFFu, v1, flat - 32);
            else                v = __shfl_sync(0xFFFFFFFFu, v2, flat - 64);

            const unsigned sh = (v & 7u) * 4u;
            const unsigned c  = (cnt >> sh) & 0xFu;
            const unsigned key = (is_slot && !taken) ? ((c << 8) | (unsigned)lane)
                                                     : 0xFFFFu;
            const unsigned best = __reduce_min_sync(0xFFFFFFFFu, key) & 0xFFu;
            if ((unsigned)lane == best) {
                taken = 1u;
                cnt  += 1u << sh;
                perm  = v;
            }
        }
        // lanes 0..4 hold this node's slot-pairs; build both parity packings
        const unsigned plo = __shfl_sync(0xFFFFFFFFu, perm, (lane << 1), 32);
        const unsigned phi = __shfl_sync(0xFFFFFFFFu, perm, (lane << 1) + 1, 32);
        const unsigned pre = (plo & 0xFFFFu) | (phi << 16);
        const unsigned plo_o = plo + ((plo < DBN) ? (unsigned)NODES : 0u);
        const unsigned phi_o = phi + ((phi < DBN) ? (unsigned)NODES : 0u);
        const unsigned pro = (plo_o & 0xFFFFu) | (phi_o << 16);

        const unsigned e1 = __shfl_sync(0xFFFFFFFFu, pre, 1);
        const unsigned e2 = __shfl_sync(0xFFFFFFFFu, pre, 2);
        const unsigned e3 = __shfl_sync(0xFFFFFFFFu, pre, 3);
        const unsigned e4 = __shfl_sync(0xFFFFFFFFu, pre, 4);
        const unsigned o1 = __shfl_sync(0xFFFFFFFFu, pro, 1);
        const unsigned o2 = __shfl_sync(0xFFFFFFFFu, pro, 2);
        const unsigned o3 = __shfl_sync(0xFFFFFFFFu, pro, 3);
        const unsigned o4 = __shfl_sync(0xFFFFFFFFu, pro, 4);
        if (lane == 0) {
            const int n = warp * 8 + ln;
            g_pk4e[n] = make_uint4(pre, e1, e2, e3);
            g_pk1e[n] = e4;
            g_pk4o[n] = make_uint4(pro, o1, o2, o3);
            g_pk1o[n] = o4;
        }
    }
}

// ---------------------------------------------------------------------------
// Fast 2*atanh (MUFU rcp+lg2; rel err ~3e-6 — proven in R14).
__device__ __forceinline__ float fast_2atanh(float p)
{
    p = fminf(0.999999f, fmaxf(-0.999999f, p));
    return __logf(__fdividef(1.0f + p, 1.0f - p));
}

// One node's Phase-B body (gather + product + 2*atanh + residual update).
__device__ __forceinline__ float4 node_update(
    const float4* __restrict__ st, const uint4 pka, const unsigned pk1,
    const float4 wl, const float2 wr, const float4 pr, const float4 c,
    bool use_prev)
{
    float4 p0 = st[pka.x & 0xFFFFu];
    float4 p1 = st[pka.x >> 16];
    {
        const float4 a = st[pka.y & 0xFFFFu];
        const float4 b = st[pka.y >> 16];
        p0.x *= a.x; p0.y *= a.y; p0.z *= a.z; p0.w *= a.w;
        p1.x *= b.x; p1.y *= b.y; p1.z *= b.z; p1.w *= b.w;
    }
    {
        const float4 a = st[pka.z & 0xFFFFu];
        const float4 b = st[pka.z >> 16];
        p0.x *= a.x; p0.y *= a.y; p0.z *= a.z; p0.w *= a.w;
        p1.x *= b.x; p1.y *= b.y; p1.z *= b.z; p1.w *= b.w;
    }
    {
        const float4 a = st[pka.w & 0xFFFFu];
        const float4 b = st[pka.w >> 16];
        p0.x *= a.x; p0.y *= a.y; p0.z *= a.z; p0.w *= a.w;
        p1.x *= b.x; p1.y *= b.y; p1.z *= b.z; p1.w *= b.w;
    }
    {
        const float4 a = st[pk1 & 0xFFFFu];
        const float4 b = st[pk1 >> 16];
        p0.x *= a.x; p0.y *= a.y; p0.z *= a.z; p0.w *= a.w;
        p1.x *= b.x; p1.y *= b.y; p1.z *= b.z; p1.w *= b.w;
    }
    float4 p;
    p.x = p0.x * p1.x;  p.y = p0.y * p1.y;
    p.z = p0.z * p1.z;  p.w = p0.w * p1.w;

    float4 nv;
    nv.x = wl.x + fast_2atanh(p.x) + wr.x * c.x;
    nv.y = wl.y + fast_2atanh(p.y) + wr.x * c.y;
    nv.z = wl.z + fast_2atanh(p.z) + wr.x * c.z;
    nv.w = wl.w + fast_2atanh(p.w) + wr.x * c.w;
    if (use_prev) {
        nv.x += wr.y * pr.x;  nv.y += wr.y * pr.y;
        nv.z += wr.y * pr.z;  nv.w += wr.y * pr.w;
    }
    return nv;
}

// ---------------------------------------------------------------------------
__global__ __launch_bounds__(TPB, 1)
void ldpc4_kernel(const float* __restrict__ input_llr,
                  const float* __restrict__ w_ch,
                  float*       __restrict__ out)
{
    extern __shared__ float4 st[];   // [0,NODES): main slots; [NODES,NODES+DBN): alt
    const int tid  = threadIdx.x;
    const int g    = blockIdx.x;
    const int row0 = g * RPC;
    const float* llr0 = input_llr + (size_t)row0 * NODES;

    float4 cur[NPT];   // current var_messages for this thread's nodes (4 rows)

    // Prologue: weighted LLR -> registers + global scratch; initial tanh -> main.
    #pragma unroll
    for (int i = 0; i < NPT; i++) {
        const int n = tid + i * TPB;
        const float wc = w_ch[n];
        float4 wl;
        wl.x = llr0[n]             * wc;
        wl.y = llr0[NODES + n]     * wc;
        wl.z = llr0[2 * NODES + n] * wc;
        wl.w = llr0[3 * NODES + n] * wc;
        g_wllr[g][n] = wl;
        cur[i] = wl;
        float4 t;
        t.x = tanhf(0.5f * wl.x);
        t.y = tanhf(0.5f * wl.y);
        t.z = tanhf(0.5f * wl.z);
        t.w = tanhf(0.5f * wl.w);
        st[n] = t;
    }
    __syncthreads();

    #pragma unroll 1
    for (int it = 0; it < ITERS; it++) {
        const uint4*        __restrict__ pk4 = (it & 1) ? g_pk4o : g_pk4e;
        const unsigned int* __restrict__ pk1 = (it & 1) ? g_pk1o : g_pk1e;
        float4* __restrict__ dbw = (it & 1) ? st : (st + NODES);  // alt slots t+1
        const bool more = (it < ITERS - 1);

        // Phase B (DB nodes, i<7): gather/update, then FUSED tanh for next
        // iteration stored to the alternate slot (untouched by this iter's
        // readers -> no barrier needed before the write).
        #pragma unroll 1
        for (int i = 0; i < NPTDB; i++) {
            const int n = tid + i * TPB;
            float4 pr = make_float4(0.f, 0.f, 0.f, 0.f);
            if (it > 0) pr = g_P[g][n];
            const float4 nv = node_update(st, pk4[n], pk1[n],
                                          g_wllr[g][n], g_wr[n], pr, cur[i], it > 0);
            if (more) g_P[g][n] = cur[i];
            cur[i] = nv;
            if (more) {
                float4 t;
                t.x = tanhf(0.5f * nv.x);
                t.y = tanhf(0.5f * nv.y);
                t.z = tanhf(0.5f * nv.z);
                t.w = tanhf(0.5f * nv.w);
                dbw[n] = t;
            }
        }

        // Phase B (tail nodes, i>=7): gather/update only.
        #pragma unroll 2
        for (int i = NPTDB; i < NPT; i++) {
            const int n = tid + i * TPB;
            float4 pr = make_float4(0.f, 0.f, 0.f, 0.f);
            if (it > 0) pr = g_P[g][n];
            const float4 nv = node_update(st, pk4[n], pk1[n],
                                          g_wllr[g][n], g_wr[n], pr, cur[i], it > 0);
            if (more) g_P[g][n] = cur[i];
            cur[i] = nv;
        }
        __syncthreads();   // all reads of this iteration's table complete

        if (more) {
            // Serial Phase A only for the non-double-buffered tail (4/11).
            #pragma unroll
            for (int i = NPTDB; i < NPT; i++) {
                const int n = tid + i * TPB;
                const float4 v = cur[i];
                float4 t;
                t.x = tanhf(0.5f * v.x);
                t.y = tanhf(0.5f * v.y);
                t.z = tanhf(0.5f * v.z);
                t.w = tanhf(0.5f * v.w);
                st[n] = t;     // main slot (read by both parities)
            }
            __syncthreads();
        }
    }

    // Epilogue: soft_bits = sigmoid(vm + input_llr), 4 coalesced row streams.
    #pragma unroll
    for (int i = 0; i < NPT; i++) {
        const int n = tid + i * TPB;
        const float4 c = cur[i];
        float* o = out + (size_t)row0 * NODES;
        const float zx = c.x + llr0[n];
        const float zy = c.y + llr0[NODES + n];
        const float zz = c.z + llr0[2 * NODES + n];
        const float zw = c.w + llr0[3 * NODES + n];
        o[n]             = 1.0f / (1.0f + expf(-zx));
        o[NODES + n]     = 1.0f / (1.0f + expf(-zy));
        o[2 * NODES + n] = 1.0f / (1.0f + expf(-zz));
        o[3 * NODES + n] = 1.0f / (1.0f + expf(-zw));
    }
}

// ---------------------------------------------------------------------------
extern "C" void kernel_launch(void* const* d_in, const int* in_sizes, int n_in,
                              void* d_out, int out_size)
{
    const float* input_llr = (const float*)d_in[0];
    const float* w_ch      = (const float*)d_in[1];
    const float* w_res     = (const float*)d_in[2];
    const int*   check_idx = (const int*)d_in[3];
    // d_in[4] (var_index_tensor) is unused by the reference computation.
    float* out = (float*)d_out;

    // one warp per group: NQG * 32 threads
    prep_sched_kernel<<<(NQG * 32 + 255) / 256, 256>>>(check_idx, w_res);

    cudaFuncSetAttribute(ldpc4_kernel,
                         cudaFuncAttributeMaxDynamicSharedMemorySize, SMEM_BYTES);
    ldpc4_kernel<<<NGROUPS, TPB, SMEM_BYTES>>>(input_llr, w_ch, out);
}